// round 1
// baseline (speedup 1.0000x reference)
#include <cuda_runtime.h>
#include <cuda_bf16.h>
#include <math.h>

#define NPV   50000
#define FDIM  128
#define HDIM  256
#define EPPI  800000
#define NPAIRS 200000
#define ETOT  (EPPI + NPV)   // edges + self loops

// ---------------- scratch (device globals; no allocation allowed) ----------
__device__ float g_hplin[(size_t)NPV * HDIM];   // xp @ Wa[2]
__device__ float g_hp[(size_t)NPV * HDIM];      // GAT-a output (accumulator)
__device__ float g_hp2lin[(size_t)NPV * FDIM];  // hp @ Wb[2]
__device__ float g_hp2[(size_t)NPV * FDIM];     // GAT-b output (accumulator)
__device__ float g_as[NPV], g_ad[NPV], g_m[NPV], g_den[NPV];
__device__ float g_s1[NPV], g_s2[NPV];

// ---------------- helpers --------------------------------------------------
__device__ __forceinline__ void atomicMaxF(float* addr, float v) {
    if (v >= 0.f) atomicMax((int*)addr, __float_as_int(v));
    else          atomicMin((unsigned int*)addr, __float_as_uint(v));
}

__global__ void fill_f(float* p, float v, int n) {
    int i = blockIdx.x * blockDim.x + threadIdx.x;
    if (i < n) p[i] = v;
}

// ---------------- tiled fp32 GEMM: C[M,N] = A[M,K] @ B[K,N] ----------------
#define BM 64
#define BN 64
#define BK 16
__global__ void sgemm_k(const float* __restrict__ A, const float* __restrict__ B,
                        float* __restrict__ C, int M, int N, int K) {
    __shared__ float As[BK][BM + 1];
    __shared__ float Bs[BK][BN + 1];
    int tid = threadIdx.x;
    int blockRow = blockIdx.y * BM;
    int blockCol = blockIdx.x * BN;
    int tr = tid / 16;   // 0..15
    int tc = tid % 16;   // 0..15
    float acc[4][4] = {};

    for (int k0 = 0; k0 < K; k0 += BK) {
        #pragma unroll
        for (int i = 0; i < 4; i++) {
            int idx = tid + i * 256;      // 0..1023 over 64x16 A tile
            int r = idx / BK;
            int c = idx % BK;
            int gr = blockRow + r;
            As[c][r] = (gr < M) ? A[(size_t)gr * K + k0 + c] : 0.f;
        }
        #pragma unroll
        for (int i = 0; i < 4; i++) {
            int idx = tid + i * 256;      // 0..1023 over 16x64 B tile
            int r = idx / BN;
            int c = idx % BN;
            Bs[r][c] = B[(size_t)(k0 + r) * N + blockCol + c];
        }
        __syncthreads();
        #pragma unroll
        for (int k = 0; k < BK; k++) {
            float a[4], b[4];
            #pragma unroll
            for (int i = 0; i < 4; i++) a[i] = As[k][tr * 4 + i];
            #pragma unroll
            for (int j = 0; j < 4; j++) b[j] = Bs[k][tc * 4 + j];
            #pragma unroll
            for (int i = 0; i < 4; i++)
                #pragma unroll
                for (int j = 0; j < 4; j++) acc[i][j] += a[i] * b[j];
        }
        __syncthreads();
    }
    #pragma unroll
    for (int i = 0; i < 4; i++) {
        int gr = blockRow + tr * 4 + i;
        if (gr < M) {
            #pragma unroll
            for (int j = 0; j < 4; j++)
                C[(size_t)gr * N + blockCol + tc * 4 + j] = acc[i][j];
        }
    }
}

// ---------------- per-node attention dot products --------------------------
// as[n] = h[n,:] . a_src ; ad[n] = h[n,:] . a_dst   (warp per node)
__global__ void attn_dots_k(const float* __restrict__ h,
                            const float* __restrict__ a_src,
                            const float* __restrict__ a_dst,
                            float* __restrict__ as_, float* __restrict__ ad_,
                            int N, int D) {
    int w = (blockIdx.x * blockDim.x + threadIdx.x) >> 5;
    int lane = threadIdx.x & 31;
    if (w >= N) return;
    const float* row = h + (size_t)w * D;
    float s = 0.f, d = 0.f;
    for (int i = lane; i < D; i += 32) {
        float v = row[i];
        s += v * a_src[i];
        d += v * a_dst[i];
    }
    #pragma unroll
    for (int o = 16; o; o >>= 1) {
        s += __shfl_down_sync(0xffffffffu, s, o);
        d += __shfl_down_sync(0xffffffffu, d, o);
    }
    if (lane == 0) { as_[w] = s; ad_[w] = d; }
}

// ---------------- edge passes (ppi edges + NPV self-loops) ------------------
__device__ __forceinline__ void edge_sd(int e, const int* src, const int* dst,
                                        int& s, int& d) {
    if (e < EPPI) { s = src[e]; d = dst[e]; }
    else          { s = d = e - EPPI; }
}
__device__ __forceinline__ float leaky(float v) { return v > 0.f ? v : 0.2f * v; }

__global__ void edge_max_k(const int* __restrict__ src, const int* __restrict__ dst,
                           const float* __restrict__ as_, const float* __restrict__ ad_,
                           float* __restrict__ m) {
    int e = blockIdx.x * blockDim.x + threadIdx.x;
    if (e >= ETOT) return;
    int s, d; edge_sd(e, src, dst, s, d);
    atomicMaxF(&m[d], leaky(as_[s] + ad_[d]));
}

__global__ void edge_sum_k(const int* __restrict__ src, const int* __restrict__ dst,
                           const float* __restrict__ as_, const float* __restrict__ ad_,
                           const float* __restrict__ m, float* __restrict__ den) {
    int e = blockIdx.x * blockDim.x + threadIdx.x;
    if (e >= ETOT) return;
    int s, d; edge_sd(e, src, dst, s, d);
    atomicAdd(&den[d], expf(leaky(as_[s] + ad_[d]) - m[d]));
}

// warp per edge: out[dst,:] += alpha * feat[src,:]
__global__ void edge_scatter_k(const int* __restrict__ src, const int* __restrict__ dst,
                               const float* __restrict__ as_, const float* __restrict__ ad_,
                               const float* __restrict__ m, const float* __restrict__ den,
                               const float* __restrict__ feat, float* __restrict__ out,
                               int D) {
    int gw = (blockIdx.x * blockDim.x + threadIdx.x) >> 5;
    int lane = threadIdx.x & 31;
    if (gw >= ETOT) return;
    int s, d; edge_sd(gw, src, dst, s, d);
    float w = expf(leaky(as_[s] + ad_[d]) - m[d]) / den[d];
    const float4* f4 = (const float4*)(feat + (size_t)s * D);
    float4* o4 = (float4*)(out + (size_t)d * D);
    int n4 = D >> 2;
    for (int i = lane; i < n4; i += 32) {
        float4 x = f4[i];
        float4 y = make_float4(w * x.x, w * x.y, w * x.z, w * x.w);
        atomicAdd(o4 + i, y);   // vector red.add (sm_90+)
    }
}

__global__ void bias_act_k(float* __restrict__ h, const float* __restrict__ b,
                           int n, int Dmask, int do_relu) {
    int i = blockIdx.x * blockDim.x + threadIdx.x;
    if (i >= n) return;
    float v = h[i] + b[i & Dmask];
    if (do_relu) v = fmaxf(v, 0.f);
    h[i] = v;
}

// ---------------- link-prediction head -------------------------------------
__global__ void head_dots_k(const float* __restrict__ h, const float* __restrict__ wout,
                            float* __restrict__ s1, float* __restrict__ s2) {
    int w = (blockIdx.x * blockDim.x + threadIdx.x) >> 5;
    int lane = threadIdx.x & 31;
    if (w >= NPV) return;
    const float* row = h + (size_t)w * FDIM;
    float a = 0.f, b = 0.f;
    for (int i = lane; i < FDIM; i += 32) {
        a += row[i] * wout[i];
        b += row[i] * wout[FDIM + i];
    }
    #pragma unroll
    for (int o = 16; o; o >>= 1) {
        a += __shfl_down_sync(0xffffffffu, a, o);
        b += __shfl_down_sync(0xffffffffu, b, o);
    }
    if (lane == 0) { s1[w] = a; s2[w] = b; }
}

__global__ void pair_head_k(const int* __restrict__ mask,
                            const float* __restrict__ s1, const float* __restrict__ s2,
                            const float* __restrict__ bout, float* __restrict__ out) {
    int p = blockIdx.x * blockDim.x + threadIdx.x;
    if (p >= NPAIRS) return;
    int i = mask[2 * p];
    int j = mask[2 * p + 1];
    float z = s1[i] + s2[j] + bout[0];
    out[p] = 1.f / (1.f + expf(-z));
}

// ---------------- launch ----------------------------------------------------
extern "C" void kernel_launch(void* const* d_in, const int* in_sizes, int n_in,
                              void* d_out, int out_size) {
    (void)in_sizes; (void)n_in; (void)out_size;
    // metadata order (live subset only)
    const float* xp    = (const float*)d_in[0];
    const int*   eippi = (const int*)d_in[5];        // [2, EPPI]: src | dst
    const int*   mask  = (const int*)d_in[6];        // [NPAIRS, 2]
    const float* Wa2   = (const float*)d_in[7]  + (size_t)2 * FDIM * HDIM;
    const float* asa   = (const float*)d_in[8]  + 2 * HDIM;
    const float* ada   = (const float*)d_in[9]  + 2 * HDIM;
    const float* ba    = (const float*)d_in[10] + 2 * HDIM;
    const float* Wb2   = (const float*)d_in[11] + (size_t)2 * HDIM * FDIM;
    const float* asb   = (const float*)d_in[12] + 2 * FDIM;
    const float* adb   = (const float*)d_in[13] + 2 * FDIM;
    const float* bb    = (const float*)d_in[14] + 2 * FDIM;
    const float* Wout  = (const float*)d_in[21];
    const float* bout  = (const float*)d_in[22];
    float* out = (float*)d_out;

    const int* e_src = eippi;
    const int* e_dst = eippi + EPPI;

    float *hplin, *hp, *hp2lin, *hp2, *pas, *pad, *pm, *pden, *ps1, *ps2;
    cudaGetSymbolAddress((void**)&hplin,  g_hplin);
    cudaGetSymbolAddress((void**)&hp,     g_hp);
    cudaGetSymbolAddress((void**)&hp2lin, g_hp2lin);
    cudaGetSymbolAddress((void**)&hp2,    g_hp2);
    cudaGetSymbolAddress((void**)&pas,    g_as);
    cudaGetSymbolAddress((void**)&pad,    g_ad);
    cudaGetSymbolAddress((void**)&pm,     g_m);
    cudaGetSymbolAddress((void**)&pden,   g_den);
    cudaGetSymbolAddress((void**)&ps1,    g_s1);
    cudaGetSymbolAddress((void**)&ps2,    g_s2);

    const int T = 256;
    const int nA = NPV * HDIM;           // 12.8M
    const int nB = NPV * FDIM;           // 6.4M
    const int edgeBlocks    = (ETOT + T - 1) / T;
    const int scatterBlocks = (ETOT * 32 + T - 1) / T;
    const int warpNodeBlk   = (NPV * 32 + T - 1) / T;

    // zero accumulators
    fill_f<<<(nA + T - 1) / T, T>>>(hp, 0.f, nA);
    fill_f<<<(nB + T - 1) / T, T>>>(hp2, 0.f, nB);

    // ===== layer a: hp = relu(GAT_ppi(xp; Wa[2]) + bias) =====
    sgemm_k<<<dim3(HDIM / BN, (NPV + BM - 1) / BM), 256>>>(xp, Wa2, hplin, NPV, HDIM, FDIM);
    attn_dots_k<<<warpNodeBlk, T>>>(hplin, asa, ada, pas, pad, NPV, HDIM);
    fill_f<<<(NPV + T - 1) / T, T>>>(pm, -INFINITY, NPV);
    fill_f<<<(NPV + T - 1) / T, T>>>(pden, 0.f, NPV);
    edge_max_k<<<edgeBlocks, T>>>(e_src, e_dst, pas, pad, pm);
    edge_sum_k<<<edgeBlocks, T>>>(e_src, e_dst, pas, pad, pm, pden);
    edge_scatter_k<<<scatterBlocks, T>>>(e_src, e_dst, pas, pad, pm, pden, hplin, hp, HDIM);
    bias_act_k<<<(nA + T - 1) / T, T>>>(hp, ba, nA, HDIM - 1, 1);

    // ===== layer b: hp2 = GAT_ppi(hp; Wb[2]) + bias =====
    sgemm_k<<<dim3(FDIM / BN, (NPV + BM - 1) / BM), 256>>>(hp, Wb2, hp2lin, NPV, FDIM, HDIM);
    attn_dots_k<<<warpNodeBlk, T>>>(hp2lin, asb, adb, pas, pad, NPV, FDIM);
    fill_f<<<(NPV + T - 1) / T, T>>>(pm, -INFINITY, NPV);
    fill_f<<<(NPV + T - 1) / T, T>>>(pden, 0.f, NPV);
    edge_max_k<<<edgeBlocks, T>>>(e_src, e_dst, pas, pad, pm);
    edge_sum_k<<<edgeBlocks, T>>>(e_src, e_dst, pas, pad, pm, pden);
    edge_scatter_k<<<scatterBlocks, T>>>(e_src, e_dst, pas, pad, pm, pden, hp2lin, hp2, FDIM);
    bias_act_k<<<(nB + T - 1) / T, T>>>(hp2, bb, nB, FDIM - 1, 0);

    // ===== head =====
    head_dots_k<<<warpNodeBlk, T>>>(hp2, Wout, ps1, ps2);
    pair_head_k<<<(NPAIRS + T - 1) / T, T>>>(mask, ps1, ps2, bout, out);
}

// round 3
// speedup vs baseline: 3.1578x; 3.1578x over previous
#include <cuda_runtime.h>
#include <cuda_bf16.h>
#include <math.h>

#define NPV    50000
#define FDIM   128
#define HDIM   256
#define EPPI   800000
#define NPAIRS 200000
#define ETOT   (EPPI + NPV)   // edges + self loops

// ---------------- scratch (device globals; no allocation allowed) ----------
__device__ float g_hplin[(size_t)NPV * HDIM];   // xp @ Wa[2]
__device__ float g_hp[(size_t)NPV * HDIM];      // GAT-a output
__device__ float g_hp2lin[(size_t)NPV * FDIM];  // hp @ Wb[2]
__device__ float g_hp2[(size_t)NPV * FDIM];     // GAT-b output
__device__ float g_as[NPV], g_ad[NPV];
__device__ float g_s1[NPV], g_s2[NPV];
// CSR scratch
__device__ int g_deg[NPV];
__device__ int g_rowptr[NPV + 1];
__device__ int g_cursor[NPV];
__device__ int g_nbr[ETOT];
__device__ int g_bsum[256];

__device__ __forceinline__ float leaky(float v) { return v > 0.f ? v : 0.2f * v; }

// ---------------- CSR build -------------------------------------------------
__device__ __forceinline__ void edge_sd(int e, const int* src, const int* dst,
                                        int& s, int& d) {
    if (e < EPPI) { s = src[e]; d = dst[e]; }
    else          { s = d = e - EPPI; }
}

__global__ void zero_i(int* p, int n) {
    int i = blockIdx.x * blockDim.x + threadIdx.x;
    if (i < n) p[i] = 0;
}

__global__ void count_k(const int* __restrict__ src, const int* __restrict__ dst,
                        int* __restrict__ deg) {
    int e = blockIdx.x * blockDim.x + threadIdx.x;
    if (e >= ETOT) return;
    int s, d; edge_sd(e, src, dst, s, d);
    atomicAdd(&deg[d], 1);
}

#define SCB 256
__global__ void scan_block_k(const int* __restrict__ deg, int* __restrict__ rowptr,
                             int* __restrict__ bsum, int n) {
    __shared__ int sh[SCB];
    int i = blockIdx.x * SCB + threadIdx.x;
    int v = (i < n) ? deg[i] : 0;
    sh[threadIdx.x] = v;
    __syncthreads();
    for (int o = 1; o < SCB; o <<= 1) {
        int t = (threadIdx.x >= o) ? sh[threadIdx.x - o] : 0;
        __syncthreads();
        sh[threadIdx.x] += t;
        __syncthreads();
    }
    if (i < n) rowptr[i] = sh[threadIdx.x] - v;   // exclusive
    if (threadIdx.x == SCB - 1) bsum[blockIdx.x] = sh[SCB - 1];
}

__global__ void scan_bsum_k(int* __restrict__ bsum, int nb) {
    __shared__ int sh[SCB];
    int v = (threadIdx.x < nb) ? bsum[threadIdx.x] : 0;
    sh[threadIdx.x] = v;
    __syncthreads();
    for (int o = 1; o < SCB; o <<= 1) {
        int t = (threadIdx.x >= o) ? sh[threadIdx.x - o] : 0;
        __syncthreads();
        sh[threadIdx.x] += t;
        __syncthreads();
    }
    if (threadIdx.x < nb) bsum[threadIdx.x] = sh[threadIdx.x] - v;  // exclusive
}

__global__ void scan_add_k(int* __restrict__ rowptr, int* __restrict__ cursor,
                           const int* __restrict__ bsum, int n) {
    int i = blockIdx.x * blockDim.x + threadIdx.x;
    if (i < n) {
        int r = rowptr[i] + bsum[i / SCB];
        rowptr[i] = r;
        cursor[i] = r;
    }
    if (i == n - 1) rowptr[n] = ETOT;
}

__global__ void place_k(const int* __restrict__ src, const int* __restrict__ dst,
                        int* __restrict__ cursor, int* __restrict__ nbr) {
    int e = blockIdx.x * blockDim.x + threadIdx.x;
    if (e >= ETOT) return;
    int s, d; edge_sd(e, src, dst, s, d);
    int pos = atomicAdd(&cursor[d], 1);
    nbr[pos] = s;
}

// ---------------- 128x128x16 SGEMM: C[M,N] = A[M,K] @ B[K,N] ----------------
#define GBM 128
#define GBN 128
#define GBK 16
__global__ __launch_bounds__(256, 2)
void sgemm_k(const float* __restrict__ A, const float* __restrict__ B,
             float* __restrict__ C, int M, int N, int K) {
    __shared__ float As[GBK][GBM + 4];
    __shared__ float Bs[GBK][GBN + 4];
    int tid = threadIdx.x;
    int blockRow = blockIdx.y * GBM;
    int blockCol = blockIdx.x * GBN;
    int tr = tid / 16;   // 0..15
    int tc = tid % 16;   // 0..15
    float acc[8][8] = {};

    for (int k0 = 0; k0 < K; k0 += GBK) {
        // A tile: 128 rows x 16 cols = 512 float4
        #pragma unroll
        for (int i = 0; i < 2; i++) {
            int idx = tid + i * 256;          // 0..511
            int r = idx >> 2;                 // 0..127
            int c4 = (idx & 3) * 4;           // 0,4,8,12
            int gr = blockRow + r;
            float4 v = make_float4(0.f, 0.f, 0.f, 0.f);
            if (gr < M) v = *(const float4*)(A + (size_t)gr * K + k0 + c4);
            As[c4 + 0][r] = v.x;
            As[c4 + 1][r] = v.y;
            As[c4 + 2][r] = v.z;
            As[c4 + 3][r] = v.w;
        }
        // B tile: 16 rows x 128 cols = 512 float4
        #pragma unroll
        for (int i = 0; i < 2; i++) {
            int idx = tid + i * 256;
            int r = idx >> 5;                 // 0..15
            int c = (idx & 31) * 4;           // 0..124
            float4 v = *(const float4*)(B + (size_t)(k0 + r) * N + blockCol + c);
            *(float4*)&Bs[r][c] = v;
        }
        __syncthreads();
        #pragma unroll
        for (int k = 0; k < GBK; k++) {
            float a[8], b[8];
            *(float4*)&a[0] = *(float4*)&As[k][tr * 8];
            *(float4*)&a[4] = *(float4*)&As[k][tr * 8 + 4];
            *(float4*)&b[0] = *(float4*)&Bs[k][tc * 8];
            *(float4*)&b[4] = *(float4*)&Bs[k][tc * 8 + 4];
            #pragma unroll
            for (int i = 0; i < 8; i++)
                #pragma unroll
                for (int j = 0; j < 8; j++) acc[i][j] += a[i] * b[j];
        }
        __syncthreads();
    }
    #pragma unroll
    for (int i = 0; i < 8; i++) {
        int gr = blockRow + tr * 8 + i;
        if (gr < M) {
            float* cr = C + (size_t)gr * N + blockCol + tc * 8;
            *(float4*)cr       = *(float4*)&acc[i][0];
            *(float4*)(cr + 4) = *(float4*)&acc[i][4];
        }
    }
}

// ---------------- per-node attention dot products ---------------------------
__global__ void attn_dots_k(const float* __restrict__ h,
                            const float* __restrict__ a_src,
                            const float* __restrict__ a_dst,
                            float* __restrict__ as_, float* __restrict__ ad_,
                            int N, int D) {
    int w = (blockIdx.x * blockDim.x + threadIdx.x) >> 5;
    int lane = threadIdx.x & 31;
    if (w >= N) return;
    const float* row = h + (size_t)w * D;
    float s = 0.f, d = 0.f;
    for (int i = lane; i < D; i += 32) {
        float v = row[i];
        s += v * a_src[i];
        d += v * a_dst[i];
    }
    #pragma unroll
    for (int o = 16; o; o >>= 1) {
        s += __shfl_down_sync(0xffffffffu, s, o);
        d += __shfl_down_sync(0xffffffffu, d, o);
    }
    if (lane == 0) { as_[w] = s; ad_[w] = d; }
}

// ---------------- fused GAT aggregate (CSR gather), warp per dst ------------
// out[d,:] = relu?( (sum_s w_s * feat[s,:]) / sum_s w_s + bias )
// VEC = D/128 float4 per lane
template <int VEC, bool RELU>
__global__ void gat_gather_k(const int* __restrict__ rowptr, const int* __restrict__ nbr,
                             const float* __restrict__ as_, const float* __restrict__ ad_,
                             const float* __restrict__ feat, const float* __restrict__ bias,
                             float* __restrict__ out) {
    int d = (blockIdx.x * blockDim.x + threadIdx.x) >> 5;
    int lane = threadIdx.x & 31;
    if (d >= NPV) return;
    int beg = rowptr[d];
    int end = rowptr[d + 1];
    float add = ad_[d];

    // pass 1: max over incident edges (lane-parallel)
    float mx = -INFINITY;
    for (int k = beg + lane; k < end; k += 32)
        mx = fmaxf(mx, leaky(as_[nbr[k]] + add));
    #pragma unroll
    for (int o = 16; o; o >>= 1)
        mx = fmaxf(mx, __shfl_xor_sync(0xffffffffu, mx, o));

    // pass 2: weighted feature accumulation (neighbors serial, features lane-parallel)
    float4 acc[VEC];
    #pragma unroll
    for (int v = 0; v < VEC; v++) acc[v] = make_float4(0.f, 0.f, 0.f, 0.f);
    float sw = 0.f;
    for (int k = beg; k < end; k++) {
        int s = nbr[k];
        float w = expf(leaky(as_[s] + add) - mx);
        sw += w;
        const float4* f = (const float4*)(feat + (size_t)s * (VEC * 128));
        #pragma unroll
        for (int v = 0; v < VEC; v++) {
            float4 x = f[lane + 32 * v];
            acc[v].x += w * x.x;
            acc[v].y += w * x.y;
            acc[v].z += w * x.z;
            acc[v].w += w * x.w;
        }
    }
    float inv = 1.f / sw;
    const float4* b4 = (const float4*)bias;
    float4* o4 = (float4*)(out + (size_t)d * (VEC * 128));
    #pragma unroll
    for (int v = 0; v < VEC; v++) {
        float4 bv = b4[lane + 32 * v];
        float4 r;
        r.x = acc[v].x * inv + bv.x;
        r.y = acc[v].y * inv + bv.y;
        r.z = acc[v].z * inv + bv.z;
        r.w = acc[v].w * inv + bv.w;
        if (RELU) {
            r.x = fmaxf(r.x, 0.f); r.y = fmaxf(r.y, 0.f);
            r.z = fmaxf(r.z, 0.f); r.w = fmaxf(r.w, 0.f);
        }
        o4[lane + 32 * v] = r;
    }
}

// ---------------- link-prediction head --------------------------------------
__global__ void head_dots_k(const float* __restrict__ h, const float* __restrict__ wout,
                            float* __restrict__ s1, float* __restrict__ s2) {
    int w = (blockIdx.x * blockDim.x + threadIdx.x) >> 5;
    int lane = threadIdx.x & 31;
    if (w >= NPV) return;
    const float* row = h + (size_t)w * FDIM;
    float a = 0.f, b = 0.f;
    for (int i = lane; i < FDIM; i += 32) {
        float v = row[i];
        a += v * wout[i];
        b += v * wout[FDIM + i];
    }
    #pragma unroll
    for (int o = 16; o; o >>= 1) {
        a += __shfl_down_sync(0xffffffffu, a, o);
        b += __shfl_down_sync(0xffffffffu, b, o);
    }
    if (lane == 0) { s1[w] = a; s2[w] = b; }
}

__global__ void pair_head_k(const int* __restrict__ mask,
                            const float* __restrict__ s1, const float* __restrict__ s2,
                            const float* __restrict__ bout, float* __restrict__ out) {
    int p = blockIdx.x * blockDim.x + threadIdx.x;
    if (p >= NPAIRS) return;
    int i = mask[2 * p];
    int j = mask[2 * p + 1];
    float z = s1[i] + s2[j] + bout[0];
    out[p] = 1.f / (1.f + expf(-z));
}

// ---------------- launch ----------------------------------------------------
extern "C" void kernel_launch(void* const* d_in, const int* in_sizes, int n_in,
                              void* d_out, int out_size) {
    (void)in_sizes; (void)n_in; (void)out_size;
    const float* xp    = (const float*)d_in[0];
    const int*   eippi = (const int*)d_in[5];        // [2, EPPI]
    const int*   mask  = (const int*)d_in[6];        // [NPAIRS, 2]
    const float* Wa2   = (const float*)d_in[7]  + (size_t)2 * FDIM * HDIM;
    const float* asa   = (const float*)d_in[8]  + 2 * HDIM;
    const float* ada   = (const float*)d_in[9]  + 2 * HDIM;
    const float* ba    = (const float*)d_in[10] + 2 * HDIM;
    const float* Wb2   = (const float*)d_in[11] + (size_t)2 * HDIM * FDIM;
    const float* asb   = (const float*)d_in[12] + 2 * FDIM;
    const float* adb   = (const float*)d_in[13] + 2 * FDIM;
    const float* bb    = (const float*)d_in[14] + 2 * FDIM;
    const float* Wout  = (const float*)d_in[21];
    const float* bout  = (const float*)d_in[22];
    float* out = (float*)d_out;

    const int* e_src = eippi;
    const int* e_dst = eippi + EPPI;

    float *hplin, *hp, *hp2lin, *hp2, *pas, *pad, *ps1, *ps2;
    int *deg, *rowptr, *cursor, *nbr, *bsum;
    cudaGetSymbolAddress((void**)&hplin,  g_hplin);
    cudaGetSymbolAddress((void**)&hp,     g_hp);
    cudaGetSymbolAddress((void**)&hp2lin, g_hp2lin);
    cudaGetSymbolAddress((void**)&hp2,    g_hp2);
    cudaGetSymbolAddress((void**)&pas,    g_as);
    cudaGetSymbolAddress((void**)&pad,    g_ad);
    cudaGetSymbolAddress((void**)&ps1,    g_s1);
    cudaGetSymbolAddress((void**)&ps2,    g_s2);
    cudaGetSymbolAddress((void**)&deg,    g_deg);
    cudaGetSymbolAddress((void**)&rowptr, g_rowptr);
    cudaGetSymbolAddress((void**)&cursor, g_cursor);
    cudaGetSymbolAddress((void**)&nbr,    g_nbr);
    cudaGetSymbolAddress((void**)&bsum,   g_bsum);

    const int T = 256;
    const int edgeBlocks  = (ETOT + T - 1) / T;
    const int nodeBlocks  = (NPV + T - 1) / T;
    const int warpNodeBlk = (NPV * 32 + T - 1) / T;
    const int scanBlocks  = (NPV + SCB - 1) / SCB;   // 196

    // ===== CSR build (shared by both layers) =====
    zero_i<<<nodeBlocks, T>>>(deg, NPV);
    count_k<<<edgeBlocks, T>>>(e_src, e_dst, deg);
    scan_block_k<<<scanBlocks, SCB>>>(deg, rowptr, bsum, NPV);
    scan_bsum_k<<<1, SCB>>>(bsum, scanBlocks);
    scan_add_k<<<nodeBlocks, T>>>(rowptr, cursor, bsum, NPV);
    place_k<<<edgeBlocks, T>>>(e_src, e_dst, cursor, nbr);

    // ===== layer a: hp = relu(GAT_ppi(xp; Wa[2]) + bias) =====
    sgemm_k<<<dim3(HDIM / GBN, (NPV + GBM - 1) / GBM), 256>>>(xp, Wa2, hplin, NPV, HDIM, FDIM);
    attn_dots_k<<<warpNodeBlk, T>>>(hplin, asa, ada, pas, pad, NPV, HDIM);
    gat_gather_k<2, true><<<warpNodeBlk, T>>>(rowptr, nbr, pas, pad, hplin, ba, hp);

    // ===== layer b: hp2 = GAT_ppi(hp; Wb[2]) + bias =====
    sgemm_k<<<dim3(FDIM / GBN, (NPV + GBM - 1) / GBM), 256>>>(hp, Wb2, hp2lin, NPV, FDIM, HDIM);
    attn_dots_k<<<warpNodeBlk, T>>>(hp2lin, asb, adb, pas, pad, NPV, FDIM);
    gat_gather_k<1, false><<<warpNodeBlk, T>>>(rowptr, nbr, pas, pad, hp2lin, bb, hp2);

    // ===== head =====
    head_dots_k<<<warpNodeBlk, T>>>(hp2, Wout, ps1, ps2);
    pair_head_k<<<(NPAIRS + T - 1) / T, T>>>(mask, ps1, ps2, bout, out);
}

// round 4
// speedup vs baseline: 3.5294x; 1.1177x over previous
#include <cuda_runtime.h>
#include <cuda_bf16.h>
#include <math.h>

#define NPV    50000
#define FDIM   128
#define HDIM   256
#define EPPI   800000
#define NPAIRS 200000
#define ETOT   (EPPI + NPV)   // edges + self loops

// ---------------- scratch (device globals; no allocation allowed) ----------
__device__ float g_agg[(size_t)NPV * FDIM];     // gathered xp (layer a, pre-GEMM)
__device__ float g_hp[(size_t)NPV * HDIM];      // relu(agg @ Wa2 + ba)
__device__ float g_hp2lin[(size_t)NPV * FDIM];  // hp @ Wb2
__device__ float g_as[NPV], g_ad[NPV];
__device__ float g_s1[NPV], g_s2[NPV];
__device__ float g_vas[FDIM], g_vad[FDIM];      // Wa2 @ att_src / att_dst
// CSR scratch
__device__ int g_deg[NPV];
__device__ int g_rowptr[NPV + 1];
__device__ int g_cursor[NPV];
__device__ int g_nbr[ETOT];
__device__ int g_bsum[256];

__device__ __forceinline__ float leaky(float v) { return v > 0.f ? v : 0.2f * v; }

// ---------------- CSR build -------------------------------------------------
__device__ __forceinline__ void edge_sd(int e, const int* src, const int* dst,
                                        int& s, int& d) {
    if (e < EPPI) { s = src[e]; d = dst[e]; }
    else          { s = d = e - EPPI; }
}

__global__ void zero_i(int* p, int n) {
    int i = blockIdx.x * blockDim.x + threadIdx.x;
    if (i < n) p[i] = 0;
}

__global__ void count_k(const int* __restrict__ src, const int* __restrict__ dst,
                        int* __restrict__ deg) {
    int e = blockIdx.x * blockDim.x + threadIdx.x;
    if (e >= ETOT) return;
    int s, d; edge_sd(e, src, dst, s, d);
    atomicAdd(&deg[d], 1);
}

#define SCB 256
__global__ void scan_block_k(const int* __restrict__ deg, int* __restrict__ rowptr,
                             int* __restrict__ bsum, int n) {
    __shared__ int sh[SCB];
    int i = blockIdx.x * SCB + threadIdx.x;
    int v = (i < n) ? deg[i] : 0;
    sh[threadIdx.x] = v;
    __syncthreads();
    for (int o = 1; o < SCB; o <<= 1) {
        int t = (threadIdx.x >= o) ? sh[threadIdx.x - o] : 0;
        __syncthreads();
        sh[threadIdx.x] += t;
        __syncthreads();
    }
    if (i < n) rowptr[i] = sh[threadIdx.x] - v;   // exclusive
    if (threadIdx.x == SCB - 1) bsum[blockIdx.x] = sh[SCB - 1];
}

__global__ void scan_bsum_k(int* __restrict__ bsum, int nb) {
    __shared__ int sh[SCB];
    int v = (threadIdx.x < nb) ? bsum[threadIdx.x] : 0;
    sh[threadIdx.x] = v;
    __syncthreads();
    for (int o = 1; o < SCB; o <<= 1) {
        int t = (threadIdx.x >= o) ? sh[threadIdx.x - o] : 0;
        __syncthreads();
        sh[threadIdx.x] += t;
        __syncthreads();
    }
    if (threadIdx.x < nb) bsum[threadIdx.x] = sh[threadIdx.x] - v;  // exclusive
}

__global__ void scan_add_k(int* __restrict__ rowptr, int* __restrict__ cursor,
                           const int* __restrict__ bsum, int n) {
    int i = blockIdx.x * blockDim.x + threadIdx.x;
    if (i < n) {
        int r = rowptr[i] + bsum[i / SCB];
        rowptr[i] = r;
        cursor[i] = r;
    }
    if (i == n - 1) rowptr[n] = ETOT;
}

__global__ void place_k(const int* __restrict__ src, const int* __restrict__ dst,
                        int* __restrict__ cursor, int* __restrict__ nbr) {
    int e = blockIdx.x * blockDim.x + threadIdx.x;
    if (e >= ETOT) return;
    int s, d; edge_sd(e, src, dst, s, d);
    int pos = atomicAdd(&cursor[d], 1);
    nbr[pos] = s;
}

// ---------------- TF32 tensor-core GEMM ------------------------------------
// C[M,N] = A[M,K] @ B[K,N], fp32 in/out, tf32 mma. Block 128x128x16, 8 warps
// (4x2), warp tile 32x64 = 2 m16-tiles x 8 n8-tiles. Shared memory holds
// fragment-packed tf32 so the mainloop is LDS.128/LDS.64 + HMMA only.
__device__ __forceinline__ unsigned f2tf32(float f) {
    unsigned r; asm("cvt.rna.tf32.f32 %0, %1;" : "=r"(r) : "f"(f)); return r;
}

__device__ __forceinline__ void mma_tf32(float* c, const uint4& a, const uint2& b) {
    asm volatile(
        "mma.sync.aligned.m16n8k8.row.col.f32.tf32.tf32.f32 "
        "{%0,%1,%2,%3}, {%4,%5,%6,%7}, {%8,%9}, {%0,%1,%2,%3};"
        : "+f"(c[0]), "+f"(c[1]), "+f"(c[2]), "+f"(c[3])
        : "r"(a.x), "r"(a.y), "r"(a.z), "r"(a.w), "r"(b.x), "r"(b.y));
}

template <bool BIAS_RELU>
__global__ __launch_bounds__(256, 2)
void gemm_tf32_k(const float* __restrict__ A, const float* __restrict__ B,
                 const float* __restrict__ bias, float* __restrict__ C,
                 int M, int N, int K) {
    // As: 8 mtiles(16) x 2 ksteps x 32 lanes x 4 slots = 2048 u32
    // Bs: 16 ntiles(8) x 2 ksteps x 32 lanes x 2 slots = 2048 u32
    __shared__ unsigned As[2048];
    __shared__ unsigned Bs[2048];
    int tid = threadIdx.x;
    int lane = tid & 31, warp = tid >> 5;
    int wr = warp >> 1, wc = warp & 1;          // 4x2 warp grid
    int gid = lane >> 2, tig = lane & 3;
    int blockRow = blockIdx.y * 128;
    int blockCol = blockIdx.x * 128;

    float acc[2][8][4];
    #pragma unroll
    for (int t = 0; t < 2; t++)
        #pragma unroll
        for (int u = 0; u < 8; u++)
            #pragma unroll
            for (int j = 0; j < 4; j++) acc[t][u][j] = 0.f;

    for (int k0 = 0; k0 < K; k0 += 16) {
        // ---- load A tile [128 x 16] into fragment-packed shared ----
        #pragma unroll
        for (int i = 0; i < 2; i++) {
            int idx = tid + i * 256;            // 0..511 float4s
            int m = idx >> 2;                   // 0..127
            int kb = (idx & 3) * 4;             // 0,4,8,12
            int gm = blockRow + m;
            float4 v = make_float4(0.f, 0.f, 0.f, 0.f);
            if (gm < M) v = *(const float4*)(A + (size_t)gm * K + k0 + kb);
            int mt = m >> 4, mi = m & 15;
            int kk = kb >> 3;                                 // 0/1
            int slot = (mi >> 3) | (((kb & 7) >> 2) << 1);    // 0..3
            int lbase = (mi & 7) * 4;                         // lane base
            unsigned* dst = &As[((mt * 2 + kk) * 32) * 4 + slot];
            dst[(lbase + 0) * 4] = f2tf32(v.x);
            dst[(lbase + 1) * 4] = f2tf32(v.y);
            dst[(lbase + 2) * 4] = f2tf32(v.z);
            dst[(lbase + 3) * 4] = f2tf32(v.w);
        }
        // ---- load B tile [16 x 128] into fragment-packed shared ----
        #pragma unroll
        for (int i = 0; i < 2; i++) {
            int idx = tid + i * 256;
            int r = idx >> 5;                   // k row 0..15
            int nb = (idx & 31) * 4;            // 0..124
            float4 v = *(const float4*)(B + (size_t)(k0 + r) * N + blockCol + nb);
            int nt = nb >> 3;
            int kk = r >> 3, ki = r & 7;
            int slot = ki >> 2;                               // 0/1
            int lbase = (nb & 7) * 4 + (ki & 3);              // lane base
            unsigned* dst = &Bs[((nt * 2 + kk) * 32) * 2 + slot];
            dst[(lbase + 0) * 2] = f2tf32(v.x);
            dst[(lbase + 4) * 2] = f2tf32(v.y);
            dst[(lbase + 8) * 2] = f2tf32(v.z);
            dst[(lbase + 12) * 2] = f2tf32(v.w);
        }
        __syncthreads();
        // ---- compute ----
        #pragma unroll
        for (int kk = 0; kk < 2; kk++) {
            uint4 a[2];
            #pragma unroll
            for (int t = 0; t < 2; t++) {
                int mt = wr * 2 + t;
                a[t] = *(const uint4*)&As[((mt * 2 + kk) * 32 + lane) * 4];
            }
            #pragma unroll
            for (int u = 0; u < 8; u++) {
                int nt = wc * 8 + u;
                uint2 b = *(const uint2*)&Bs[((nt * 2 + kk) * 32 + lane) * 2];
                mma_tf32(acc[0][u], a[0], b);
                mma_tf32(acc[1][u], a[1], b);
            }
        }
        __syncthreads();
    }

    // ---- epilogue ----
    #pragma unroll
    for (int t = 0; t < 2; t++) {
        int r0 = blockRow + wr * 32 + t * 16 + gid;
        int r1 = r0 + 8;
        #pragma unroll
        for (int u = 0; u < 8; u++) {
            int c = blockCol + wc * 64 + u * 8 + tig * 2;
            float b0 = 0.f, b1 = 0.f;
            if (BIAS_RELU) { b0 = bias[c]; b1 = bias[c + 1]; }
            float v0 = acc[t][u][0] + b0, v1 = acc[t][u][1] + b1;
            float v2 = acc[t][u][2] + b0, v3 = acc[t][u][3] + b1;
            if (BIAS_RELU) {
                v0 = fmaxf(v0, 0.f); v1 = fmaxf(v1, 0.f);
                v2 = fmaxf(v2, 0.f); v3 = fmaxf(v3, 0.f);
            }
            if (r0 < M) { float2 p = make_float2(v0, v1); *(float2*)(C + (size_t)r0 * N + c) = p; }
            if (r1 < M) { float2 p = make_float2(v2, v3); *(float2*)(C + (size_t)r1 * N + c) = p; }
        }
    }
}

// ---------------- attention vectors for layer a -----------------------------
// vs[f] = sum_h W[f,h]*a_s[h]; vd[f] = sum_h W[f,h]*a_d[h]   (warp per f)
__global__ void attn_matvec_k(const float* __restrict__ W,
                              const float* __restrict__ a_s, const float* __restrict__ a_d,
                              float* __restrict__ vs, float* __restrict__ vd) {
    int f = blockIdx.x * 8 + (threadIdx.x >> 5);
    int lane = threadIdx.x & 31;
    if (f >= FDIM) return;
    const float* row = W + (size_t)f * HDIM;
    float s = 0.f, d = 0.f;
    for (int h = lane; h < HDIM; h += 32) {
        float w = row[h];
        s += w * a_s[h];
        d += w * a_d[h];
    }
    #pragma unroll
    for (int o = 16; o; o >>= 1) {
        s += __shfl_down_sync(0xffffffffu, s, o);
        d += __shfl_down_sync(0xffffffffu, d, o);
    }
    if (lane == 0) { vs[f] = s; vd[f] = d; }
}

// ---------------- per-node attention dot products (D=128) -------------------
__global__ void attn_dots_k(const float* __restrict__ h,
                            const float* __restrict__ a_src,
                            const float* __restrict__ a_dst,
                            float* __restrict__ as_, float* __restrict__ ad_) {
    int w = (blockIdx.x * blockDim.x + threadIdx.x) >> 5;
    int lane = threadIdx.x & 31;
    if (w >= NPV) return;
    const float4* row = (const float4*)(h + (size_t)w * FDIM);
    float4 x = row[lane];
    float4 us = ((const float4*)a_src)[lane];
    float4 ud = ((const float4*)a_dst)[lane];
    float s = x.x * us.x + x.y * us.y + x.z * us.z + x.w * us.w;
    float d = x.x * ud.x + x.y * ud.y + x.z * ud.z + x.w * ud.w;
    #pragma unroll
    for (int o = 16; o; o >>= 1) {
        s += __shfl_down_sync(0xffffffffu, s, o);
        d += __shfl_down_sync(0xffffffffu, d, o);
    }
    if (lane == 0) { as_[w] = s; ad_[w] = d; }
}

// ---------------- layer-a gather: agg[d,:] = softmax-weighted avg of xp ----
__global__ void gather_feat_k(const int* __restrict__ rowptr, const int* __restrict__ nbr,
                              const float* __restrict__ as_, const float* __restrict__ ad_,
                              const float* __restrict__ feat, float* __restrict__ out) {
    int d = (blockIdx.x * blockDim.x + threadIdx.x) >> 5;
    int lane = threadIdx.x & 31;
    if (d >= NPV) return;
    int beg = rowptr[d];
    int end = rowptr[d + 1];
    float add = ad_[d];

    float mx = -INFINITY;
    for (int k = beg + lane; k < end; k += 32)
        mx = fmaxf(mx, leaky(as_[nbr[k]] + add));
    #pragma unroll
    for (int o = 16; o; o >>= 1)
        mx = fmaxf(mx, __shfl_xor_sync(0xffffffffu, mx, o));

    float4 acc = make_float4(0.f, 0.f, 0.f, 0.f);
    float sw = 0.f;
    for (int k = beg; k < end; k++) {
        int s = nbr[k];
        float w = expf(leaky(as_[s] + add) - mx);
        sw += w;
        float4 x = ((const float4*)(feat + (size_t)s * FDIM))[lane];
        acc.x += w * x.x; acc.y += w * x.y; acc.z += w * x.z; acc.w += w * x.w;
    }
    float inv = 1.f / sw;
    float4 r = make_float4(acc.x * inv, acc.y * inv, acc.z * inv, acc.w * inv);
    ((float4*)(out + (size_t)d * FDIM))[lane] = r;
}

// ---------------- layer-b gather fused with head dots -----------------------
// hp2[d,:] = gathered(hp2lin) + bias;  s1[d]=hp2.wout[0:128]; s2[d]=hp2.wout[128:256]
__global__ void gather_head_k(const int* __restrict__ rowptr, const int* __restrict__ nbr,
                              const float* __restrict__ as_, const float* __restrict__ ad_,
                              const float* __restrict__ feat, const float* __restrict__ bias,
                              const float* __restrict__ wout,
                              float* __restrict__ s1, float* __restrict__ s2) {
    int d = (blockIdx.x * blockDim.x + threadIdx.x) >> 5;
    int lane = threadIdx.x & 31;
    if (d >= NPV) return;
    int beg = rowptr[d];
    int end = rowptr[d + 1];
    float add = ad_[d];

    float mx = -INFINITY;
    for (int k = beg + lane; k < end; k += 32)
        mx = fmaxf(mx, leaky(as_[nbr[k]] + add));
    #pragma unroll
    for (int o = 16; o; o >>= 1)
        mx = fmaxf(mx, __shfl_xor_sync(0xffffffffu, mx, o));

    float4 acc = make_float4(0.f, 0.f, 0.f, 0.f);
    float sw = 0.f;
    for (int k = beg; k < end; k++) {
        int s = nbr[k];
        float w = expf(leaky(as_[s] + add) - mx);
        sw += w;
        float4 x = ((const float4*)(feat + (size_t)s * FDIM))[lane];
        acc.x += w * x.x; acc.y += w * x.y; acc.z += w * x.z; acc.w += w * x.w;
    }
    float inv = 1.f / sw;
    float4 bv = ((const float4*)bias)[lane];
    float4 r;
    r.x = acc.x * inv + bv.x;
    r.y = acc.y * inv + bv.y;
    r.z = acc.z * inv + bv.z;
    r.w = acc.w * inv + bv.w;
    float4 w1 = ((const float4*)wout)[lane];
    float4 w2 = ((const float4*)(wout + FDIM))[lane];
    float p1 = r.x * w1.x + r.y * w1.y + r.z * w1.z + r.w * w1.w;
    float p2 = r.x * w2.x + r.y * w2.y + r.z * w2.z + r.w * w2.w;
    #pragma unroll
    for (int o = 16; o; o >>= 1) {
        p1 += __shfl_down_sync(0xffffffffu, p1, o);
        p2 += __shfl_down_sync(0xffffffffu, p2, o);
    }
    if (lane == 0) { s1[d] = p1; s2[d] = p2; }
}

__global__ void pair_head_k(const int* __restrict__ mask,
                            const float* __restrict__ s1, const float* __restrict__ s2,
                            const float* __restrict__ bout, float* __restrict__ out) {
    int p = blockIdx.x * blockDim.x + threadIdx.x;
    if (p >= NPAIRS) return;
    int i = mask[2 * p];
    int j = mask[2 * p + 1];
    float z = s1[i] + s2[j] + bout[0];
    out[p] = 1.f / (1.f + expf(-z));
}

// ---------------- launch ----------------------------------------------------
extern "C" void kernel_launch(void* const* d_in, const int* in_sizes, int n_in,
                              void* d_out, int out_size) {
    (void)in_sizes; (void)n_in; (void)out_size;
    const float* xp    = (const float*)d_in[0];
    const int*   eippi = (const int*)d_in[5];        // [2, EPPI]
    const int*   mask  = (const int*)d_in[6];        // [NPAIRS, 2]
    const float* Wa2   = (const float*)d_in[7]  + (size_t)2 * FDIM * HDIM;
    const float* asa   = (const float*)d_in[8]  + 2 * HDIM;
    const float* ada   = (const float*)d_in[9]  + 2 * HDIM;
    const float* ba    = (const float*)d_in[10] + 2 * HDIM;
    const float* Wb2   = (const float*)d_in[11] + (size_t)2 * HDIM * FDIM;
    const float* asb   = (const float*)d_in[12] + 2 * FDIM;
    const float* adb   = (const float*)d_in[13] + 2 * FDIM;
    const float* bb    = (const float*)d_in[14] + 2 * FDIM;
    const float* Wout  = (const float*)d_in[21];
    const float* bout  = (const float*)d_in[22];
    float* out = (float*)d_out;

    const int* e_src = eippi;
    const int* e_dst = eippi + EPPI;

    float *agg, *hp, *hp2lin, *pas, *pad, *ps1, *ps2, *pvas, *pvad;
    int *deg, *rowptr, *cursor, *nbr, *bsum;
    cudaGetSymbolAddress((void**)&agg,    g_agg);
    cudaGetSymbolAddress((void**)&hp,     g_hp);
    cudaGetSymbolAddress((void**)&hp2lin, g_hp2lin);
    cudaGetSymbolAddress((void**)&pas,    g_as);
    cudaGetSymbolAddress((void**)&pad,    g_ad);
    cudaGetSymbolAddress((void**)&ps1,    g_s1);
    cudaGetSymbolAddress((void**)&ps2,    g_s2);
    cudaGetSymbolAddress((void**)&pvas,   g_vas);
    cudaGetSymbolAddress((void**)&pvad,   g_vad);
    cudaGetSymbolAddress((void**)&deg,    g_deg);
    cudaGetSymbolAddress((void**)&rowptr, g_rowptr);
    cudaGetSymbolAddress((void**)&cursor, g_cursor);
    cudaGetSymbolAddress((void**)&nbr,    g_nbr);
    cudaGetSymbolAddress((void**)&bsum,   g_bsum);

    const int T = 256;
    const int edgeBlocks  = (ETOT + T - 1) / T;
    const int nodeBlocks  = (NPV + T - 1) / T;
    const int warpNodeBlk = (NPV * 32 + T - 1) / T;
    const int scanBlocks  = (NPV + SCB - 1) / SCB;

    // ===== CSR build (shared by both layers) =====
    zero_i<<<nodeBlocks, T>>>(deg, NPV);
    count_k<<<edgeBlocks, T>>>(e_src, e_dst, deg);
    scan_block_k<<<scanBlocks, SCB>>>(deg, rowptr, bsum, NPV);
    scan_bsum_k<<<1, SCB>>>(bsum, scanBlocks);
    scan_add_k<<<nodeBlocks, T>>>(rowptr, cursor, bsum, NPV);
    place_k<<<edgeBlocks, T>>>(e_src, e_dst, cursor, nbr);

    // ===== layer a: hp = relu( gather(xp) @ Wa2 + ba ) =====
    attn_matvec_k<<<16, 256>>>(Wa2, asa, ada, pvas, pvad);
    attn_dots_k<<<warpNodeBlk, T>>>(xp, pvas, pvad, pas, pad);
    gather_feat_k<<<warpNodeBlk, T>>>(rowptr, nbr, pas, pad, xp, agg);
    gemm_tf32_k<true><<<dim3(HDIM / 128, (NPV + 127) / 128), 256>>>(
        agg, Wa2, ba, hp, NPV, HDIM, FDIM);

    // ===== layer b: hp2lin = hp @ Wb2; gather + bias + head fused =====
    gemm_tf32_k<false><<<dim3(FDIM / 128, (NPV + 127) / 128), 256>>>(
        hp, Wb2, (const float*)0, hp2lin, NPV, FDIM, HDIM);
    attn_dots_k<<<warpNodeBlk, T>>>(hp2lin, asb, adb, pas, pad);
    gather_head_k<<<warpNodeBlk, T>>>(rowptr, nbr, pas, pad, hp2lin, bb, Wout, ps1, ps2);

    // ===== head =====
    pair_head_k<<<(NPAIRS + T - 1) / T, T>>>(mask, ps1, ps2, bout, out);
}

// round 5
// speedup vs baseline: 6.2838x; 1.7804x over previous
#include <cuda_runtime.h>
#include <cuda_bf16.h>
#include <math.h>

#define NPV    50000
#define FDIM   128
#define HDIM   256
#define EPPI   800000
#define NPAIRS 200000
#define ETOT   (EPPI + NPV)   // edges + self loops

// ---------------- scratch (device globals; no allocation allowed) ----------
__device__ float g_agg[(size_t)NPV * FDIM];   // gathered xp (layer a, pre-GEMM)
__device__ float g_as[NPV], g_ad[NPV];        // layer-a attention scores
__device__ float g_q[4 * NPV];                // layer-b scalars: [0]=qs [1]=qd [2]=q1 [3]=q2
__device__ float g_s1[NPV], g_s2[NPV];
__device__ float g_vas[FDIM], g_vad[FDIM];    // Wa2 @ att vectors (layer a)
__device__ float g_cb[4 * HDIM];              // Wb2 @ {asb, adb, w1, w2}
__device__ float g_hb[2];                     // bb.w1, bb.w2
// CSR scratch
__device__ int g_deg[NPV];
__device__ int g_rowptr[NPV + 1];
__device__ int g_cursor[NPV];
__device__ int g_nbr[ETOT];
__device__ int g_bsum[256];

__device__ __forceinline__ float leaky(float v) { return v > 0.f ? v : 0.2f * v; }

// ---------------- CSR build -------------------------------------------------
__device__ __forceinline__ void edge_sd(int e, const int* src, const int* dst,
                                        int& s, int& d) {
    if (e < EPPI) { s = src[e]; d = dst[e]; }
    else          { s = d = e - EPPI; }
}

__global__ void zero_i(int* p, int n) {
    int i = blockIdx.x * blockDim.x + threadIdx.x;
    if (i < n) p[i] = 0;
}
__global__ void zero_f(float* p, int n) {
    int i = blockIdx.x * blockDim.x + threadIdx.x;
    if (i < n) p[i] = 0.f;
}

__global__ void count_k(const int* __restrict__ src, const int* __restrict__ dst,
                        int* __restrict__ deg) {
    int e = blockIdx.x * blockDim.x + threadIdx.x;
    if (e >= ETOT) return;
    int s, d; edge_sd(e, src, dst, s, d);
    atomicAdd(&deg[d], 1);
}

#define SCB 256
__global__ void scan_block_k(const int* __restrict__ deg, int* __restrict__ rowptr,
                             int* __restrict__ bsum, int n) {
    __shared__ int sh[SCB];
    int i = blockIdx.x * SCB + threadIdx.x;
    int v = (i < n) ? deg[i] : 0;
    sh[threadIdx.x] = v;
    __syncthreads();
    for (int o = 1; o < SCB; o <<= 1) {
        int t = (threadIdx.x >= o) ? sh[threadIdx.x - o] : 0;
        __syncthreads();
        sh[threadIdx.x] += t;
        __syncthreads();
    }
    if (i < n) rowptr[i] = sh[threadIdx.x] - v;   // exclusive
    if (threadIdx.x == SCB - 1) bsum[blockIdx.x] = sh[SCB - 1];
}

__global__ void scan_bsum_k(int* __restrict__ bsum, int nb) {
    __shared__ int sh[SCB];
    int v = (threadIdx.x < nb) ? bsum[threadIdx.x] : 0;
    sh[threadIdx.x] = v;
    __syncthreads();
    for (int o = 1; o < SCB; o <<= 1) {
        int t = (threadIdx.x >= o) ? sh[threadIdx.x - o] : 0;
        __syncthreads();
        sh[threadIdx.x] += t;
        __syncthreads();
    }
    if (threadIdx.x < nb) bsum[threadIdx.x] = sh[threadIdx.x] - v;  // exclusive
}

__global__ void scan_add_k(int* __restrict__ rowptr, int* __restrict__ cursor,
                           const int* __restrict__ bsum, int n) {
    int i = blockIdx.x * blockDim.x + threadIdx.x;
    if (i < n) {
        int r = rowptr[i] + bsum[i / SCB];
        rowptr[i] = r;
        cursor[i] = r;
    }
    if (i == n - 1) rowptr[n] = ETOT;
}

__global__ void place_k(const int* __restrict__ src, const int* __restrict__ dst,
                        int* __restrict__ cursor, int* __restrict__ nbr) {
    int e = blockIdx.x * blockDim.x + threadIdx.x;
    if (e >= ETOT) return;
    int s, d; edge_sd(e, src, dst, s, d);
    int pos = atomicAdd(&cursor[d], 1);
    nbr[pos] = s;
}

// ---------------- vector precompute -----------------------------------------
// warp tasks: [0,128): vas/vad rows of Wa2 . {asa,ada}
//             [128,384): cb[j][h] = Wb2 row h . {asb,adb,w1,w2}
//             384: hb = bb . {w1,w2}
__global__ void setup_vecs_k(const float* __restrict__ Wa2,
                             const float* __restrict__ asa, const float* __restrict__ ada,
                             const float* __restrict__ Wb2,
                             const float* __restrict__ asb, const float* __restrict__ adb,
                             const float* __restrict__ wout, const float* __restrict__ bb,
                             float* __restrict__ vas, float* __restrict__ vad,
                             float* __restrict__ cb, float* __restrict__ hb) {
    int gw = (blockIdx.x * blockDim.x + threadIdx.x) >> 5;
    int lane = threadIdx.x & 31;
    if (gw < 128) {
        const float* row = Wa2 + (size_t)gw * HDIM;
        float s = 0.f, d = 0.f;
        for (int h = lane; h < HDIM; h += 32) {
            float w = row[h];
            s += w * asa[h]; d += w * ada[h];
        }
        #pragma unroll
        for (int o = 16; o; o >>= 1) {
            s += __shfl_down_sync(0xffffffffu, s, o);
            d += __shfl_down_sync(0xffffffffu, d, o);
        }
        if (lane == 0) { vas[gw] = s; vad[gw] = d; }
    } else if (gw < 384) {
        int h = gw - 128;
        const float* row = Wb2 + (size_t)h * FDIM;
        float a = 0.f, b = 0.f, c = 0.f, e = 0.f;
        for (int f = lane; f < FDIM; f += 32) {
            float w = row[f];
            a += w * asb[f]; b += w * adb[f];
            c += w * wout[f]; e += w * wout[FDIM + f];
        }
        #pragma unroll
        for (int o = 16; o; o >>= 1) {
            a += __shfl_down_sync(0xffffffffu, a, o);
            b += __shfl_down_sync(0xffffffffu, b, o);
            c += __shfl_down_sync(0xffffffffu, c, o);
            e += __shfl_down_sync(0xffffffffu, e, o);
        }
        if (lane == 0) {
            cb[0 * HDIM + h] = a; cb[1 * HDIM + h] = b;
            cb[2 * HDIM + h] = c; cb[3 * HDIM + h] = e;
        }
    } else if (gw == 384) {
        float a = 0.f, b = 0.f;
        for (int f = lane; f < FDIM; f += 32) {
            float w = bb[f];
            a += w * wout[f]; b += w * wout[FDIM + f];
        }
        #pragma unroll
        for (int o = 16; o; o >>= 1) {
            a += __shfl_down_sync(0xffffffffu, a, o);
            b += __shfl_down_sync(0xffffffffu, b, o);
        }
        if (lane == 0) { hb[0] = a; hb[1] = b; }
    }
}

// ---------------- per-node attention dots over xp (D=128) -------------------
__global__ void attn_dots_k(const float* __restrict__ h,
                            const float* __restrict__ a_src,
                            const float* __restrict__ a_dst,
                            float* __restrict__ as_, float* __restrict__ ad_) {
    int w = (blockIdx.x * blockDim.x + threadIdx.x) >> 5;
    int lane = threadIdx.x & 31;
    if (w >= NPV) return;
    float4 x = ((const float4*)(h + (size_t)w * FDIM))[lane];
    float4 us = ((const float4*)a_src)[lane];
    float4 ud = ((const float4*)a_dst)[lane];
    float s = x.x * us.x + x.y * us.y + x.z * us.z + x.w * us.w;
    float d = x.x * ud.x + x.y * ud.y + x.z * ud.z + x.w * ud.w;
    #pragma unroll
    for (int o = 16; o; o >>= 1) {
        s += __shfl_down_sync(0xffffffffu, s, o);
        d += __shfl_down_sync(0xffffffffu, d, o);
    }
    if (lane == 0) { as_[w] = s; ad_[w] = d; }
}

// ---------------- layer-a gather: agg[d,:] = softmax-weighted avg of xp -----
__global__ void gather_feat_k(const int* __restrict__ rowptr, const int* __restrict__ nbr,
                              const float* __restrict__ as_, const float* __restrict__ ad_,
                              const float* __restrict__ feat, float* __restrict__ out) {
    int d = (blockIdx.x * blockDim.x + threadIdx.x) >> 5;
    int lane = threadIdx.x & 31;
    if (d >= NPV) return;
    int beg = rowptr[d];
    int end = rowptr[d + 1];
    float add = ad_[d];

    float mx = -INFINITY;
    for (int k = beg + lane; k < end; k += 32)
        mx = fmaxf(mx, leaky(as_[nbr[k]] + add));
    #pragma unroll
    for (int o = 16; o; o >>= 1)
        mx = fmaxf(mx, __shfl_xor_sync(0xffffffffu, mx, o));

    float4 acc = make_float4(0.f, 0.f, 0.f, 0.f);
    float sw = 0.f;
    const float4* f4 = (const float4*)feat;
    int k = beg;
    for (; k + 2 <= end; k += 2) {
        int s0 = nbr[k], s1 = nbr[k + 1];
        float4 x0 = f4[(size_t)s0 * 32 + lane];
        float4 x1 = f4[(size_t)s1 * 32 + lane];
        float w0 = expf(leaky(as_[s0] + add) - mx);
        float w1 = expf(leaky(as_[s1] + add) - mx);
        sw += w0 + w1;
        acc.x += w0 * x0.x + w1 * x1.x;
        acc.y += w0 * x0.y + w1 * x1.y;
        acc.z += w0 * x0.z + w1 * x1.z;
        acc.w += w0 * x0.w + w1 * x1.w;
    }
    if (k < end) {
        int s0 = nbr[k];
        float4 x0 = f4[(size_t)s0 * 32 + lane];
        float w0 = expf(leaky(as_[s0] + add) - mx);
        sw += w0;
        acc.x += w0 * x0.x; acc.y += w0 * x0.y;
        acc.z += w0 * x0.z; acc.w += w0 * x0.w;
    }
    float inv = 1.f / sw;
    ((float4*)(out + (size_t)d * FDIM))[lane] =
        make_float4(acc.x * inv, acc.y * inv, acc.z * inv, acc.w * inv);
}

// ---------------- TF32 GEMM with fused relu+4-dot epilogue -------------------
// acc = A[M,128] @ Wa2[128,256] (block 128x128, grid.x=2). Epilogue:
// v = relu(acc + ba[col]); q[j][row] += v . cb[j][cols of this block] (atomic).
// hp is NEVER materialized.
__device__ __forceinline__ unsigned f2tf32(float f) {
    unsigned r; asm("cvt.rna.tf32.f32 %0, %1;" : "=r"(r) : "f"(f)); return r;
}
__device__ __forceinline__ void mma_tf32(float* c, const uint4& a, const uint2& b) {
    asm volatile(
        "mma.sync.aligned.m16n8k8.row.col.f32.tf32.tf32.f32 "
        "{%0,%1,%2,%3}, {%4,%5,%6,%7}, {%8,%9}, {%0,%1,%2,%3};"
        : "+f"(c[0]), "+f"(c[1]), "+f"(c[2]), "+f"(c[3])
        : "r"(a.x), "r"(a.y), "r"(a.z), "r"(a.w), "r"(b.x), "r"(b.y));
}

__global__ __launch_bounds__(256, 2)
void gemm_fused_k(const float* __restrict__ A, const float* __restrict__ B,
                  const float* __restrict__ bias, const float* __restrict__ cb,
                  float* __restrict__ q, int M, int N, int K) {
    __shared__ unsigned As[2048];
    __shared__ unsigned Bs[2048];
    __shared__ float cbS[4 * 128];
    __shared__ float baS[128];
    int tid = threadIdx.x;
    int lane = tid & 31, warp = tid >> 5;
    int wr = warp >> 1, wc = warp & 1;
    int gid = lane >> 2, tig = lane & 3;
    int blockRow = blockIdx.y * 128;
    int blockCol = blockIdx.x * 128;

    // stage epilogue vectors
    #pragma unroll
    for (int i = 0; i < 2; i++) {
        int idx = tid + i * 256;               // 0..511
        int j = idx >> 7, cl = idx & 127;
        cbS[idx] = cb[j * HDIM + blockCol + cl];
    }
    if (tid < 128) baS[tid] = bias[blockCol + tid];

    float acc[2][8][4];
    #pragma unroll
    for (int t = 0; t < 2; t++)
        #pragma unroll
        for (int u = 0; u < 8; u++)
            #pragma unroll
            for (int j = 0; j < 4; j++) acc[t][u][j] = 0.f;

    float4 pa[2], pb[2];
    auto loadAB = [&](int k0) {
        #pragma unroll
        for (int i = 0; i < 2; i++) {
            int idx = tid + i * 256;
            int m = idx >> 2, kb = (idx & 3) * 4;
            int gm = blockRow + m;
            pa[i] = (gm < M) ? *(const float4*)(A + (size_t)gm * K + k0 + kb)
                             : make_float4(0.f, 0.f, 0.f, 0.f);
        }
        #pragma unroll
        for (int i = 0; i < 2; i++) {
            int idx = tid + i * 256;
            int r = idx >> 5, nb = (idx & 31) * 4;
            pb[i] = *(const float4*)(B + (size_t)(k0 + r) * N + blockCol + nb);
        }
    };
    auto storeAB = [&]() {
        #pragma unroll
        for (int i = 0; i < 2; i++) {
            int idx = tid + i * 256;
            int m = idx >> 2, kb = (idx & 3) * 4;
            int mt = m >> 4, mi = m & 15;
            int kk = kb >> 3;
            int slot = (mi >> 3) | (((kb & 7) >> 2) << 1);
            int lbase = (mi & 7) * 4;
            unsigned* dst = &As[((mt * 2 + kk) * 32) * 4 + slot];
            dst[(lbase + 0) * 4] = f2tf32(pa[i].x);
            dst[(lbase + 1) * 4] = f2tf32(pa[i].y);
            dst[(lbase + 2) * 4] = f2tf32(pa[i].z);
            dst[(lbase + 3) * 4] = f2tf32(pa[i].w);
        }
        #pragma unroll
        for (int i = 0; i < 2; i++) {
            int idx = tid + i * 256;
            int r = idx >> 5, nb = (idx & 31) * 4;
            int nt = nb >> 3;
            int kk = r >> 3, ki = r & 7;
            int slot = ki >> 2;
            int lbase = (nb & 7) * 4 + (ki & 3);
            unsigned* dst = &Bs[((nt * 2 + kk) * 32) * 2 + slot];
            dst[(lbase + 0) * 2] = f2tf32(pb[i].x);
            dst[(lbase + 4) * 2] = f2tf32(pb[i].y);
            dst[(lbase + 8) * 2] = f2tf32(pb[i].z);
            dst[(lbase + 12) * 2] = f2tf32(pb[i].w);
        }
    };

    loadAB(0);
    for (int k0 = 0; k0 < K; k0 += 16) {
        storeAB();
        __syncthreads();
        if (k0 + 16 < K) loadAB(k0 + 16);
        #pragma unroll
        for (int kk = 0; kk < 2; kk++) {
            uint4 a[2];
            #pragma unroll
            for (int t = 0; t < 2; t++) {
                int mt = wr * 2 + t;
                a[t] = *(const uint4*)&As[((mt * 2 + kk) * 32 + lane) * 4];
            }
            #pragma unroll
            for (int u = 0; u < 8; u++) {
                int nt = wc * 8 + u;
                uint2 b = *(const uint2*)&Bs[((nt * 2 + kk) * 32 + lane) * 2];
                mma_tf32(acc[0][u], a[0], b);
                mma_tf32(acc[1][u], a[1], b);
            }
        }
        __syncthreads();
    }

    // ---- fused epilogue: relu + 4 dot partials, no hp write ----
    float p[16];                     // [j][t][r] -> j*4 + t*2 + r
    #pragma unroll
    for (int i = 0; i < 16; i++) p[i] = 0.f;
    #pragma unroll
    for (int t = 0; t < 2; t++) {
        #pragma unroll
        for (int u = 0; u < 8; u++) {
            int cl = wc * 64 + u * 8 + tig * 2;
            float b0 = baS[cl], b1 = baS[cl + 1];
            float v0 = fmaxf(acc[t][u][0] + b0, 0.f);
            float v1 = fmaxf(acc[t][u][1] + b1, 0.f);
            float v2 = fmaxf(acc[t][u][2] + b0, 0.f);
            float v3 = fmaxf(acc[t][u][3] + b1, 0.f);
            #pragma unroll
            for (int j = 0; j < 4; j++) {
                float c0 = cbS[j * 128 + cl], c1 = cbS[j * 128 + cl + 1];
                p[j * 4 + t * 2 + 0] += v0 * c0 + v1 * c1;
                p[j * 4 + t * 2 + 1] += v2 * c0 + v3 * c1;
            }
        }
    }
    #pragma unroll
    for (int i = 0; i < 16; i++) {
        p[i] += __shfl_xor_sync(0xffffffffu, p[i], 1);
        p[i] += __shfl_xor_sync(0xffffffffu, p[i], 2);
    }
    if (tig == 0) {
        #pragma unroll
        for (int t = 0; t < 2; t++) {
            int r0 = blockRow + wr * 32 + t * 16 + gid;
            int r1 = r0 + 8;
            if (r0 < M) {
                #pragma unroll
                for (int j = 0; j < 4; j++)
                    atomicAdd(&q[j * NPV + r0], p[j * 4 + t * 2 + 0]);
            }
            if (r1 < M) {
                #pragma unroll
                for (int j = 0; j < 4; j++)
                    atomicAdd(&q[j * NPV + r1], p[j * 4 + t * 2 + 1]);
            }
        }
    }
}

// ---------------- layer-b scalar gather + head dots --------------------------
__global__ void gather_scalar_k(const int* __restrict__ rowptr, const int* __restrict__ nbr,
                                const float* __restrict__ q, const float* __restrict__ hb,
                                float* __restrict__ s1, float* __restrict__ s2) {
    int d = (blockIdx.x * blockDim.x + threadIdx.x) >> 5;
    int lane = threadIdx.x & 31;
    if (d >= NPV) return;
    const float* qs = q;
    const float* qd = q + NPV;
    const float* q1 = q + 2 * NPV;
    const float* q2 = q + 3 * NPV;
    int beg = rowptr[d];
    int end = rowptr[d + 1];
    float add = qd[d];

    float mx = -INFINITY;
    for (int k = beg + lane; k < end; k += 32)
        mx = fmaxf(mx, leaky(qs[nbr[k]] + add));
    #pragma unroll
    for (int o = 16; o; o >>= 1)
        mx = fmaxf(mx, __shfl_xor_sync(0xffffffffu, mx, o));

    float sw = 0.f, a1 = 0.f, a2 = 0.f;
    for (int k = beg + lane; k < end; k += 32) {
        int s = nbr[k];
        float w = expf(leaky(qs[s] + add) - mx);
        sw += w;
        a1 += w * q1[s];
        a2 += w * q2[s];
    }
    #pragma unroll
    for (int o = 16; o; o >>= 1) {
        sw += __shfl_down_sync(0xffffffffu, sw, o);
        a1 += __shfl_down_sync(0xffffffffu, a1, o);
        a2 += __shfl_down_sync(0xffffffffu, a2, o);
    }
    if (lane == 0) {
        float inv = 1.f / sw;
        s1[d] = a1 * inv + hb[0];
        s2[d] = a2 * inv + hb[1];
    }
}

__global__ void pair_head_k(const int* __restrict__ mask,
                            const float* __restrict__ s1, const float* __restrict__ s2,
                            const float* __restrict__ bout, float* __restrict__ out) {
    int p = blockIdx.x * blockDim.x + threadIdx.x;
    if (p >= NPAIRS) return;
    int i = mask[2 * p];
    int j = mask[2 * p + 1];
    float z = s1[i] + s2[j] + bout[0];
    out[p] = 1.f / (1.f + expf(-z));
}

// ---------------- launch ----------------------------------------------------
extern "C" void kernel_launch(void* const* d_in, const int* in_sizes, int n_in,
                              void* d_out, int out_size) {
    (void)in_sizes; (void)n_in; (void)out_size;
    const float* xp    = (const float*)d_in[0];
    const int*   eippi = (const int*)d_in[5];        // [2, EPPI]
    const int*   mask  = (const int*)d_in[6];        // [NPAIRS, 2]
    const float* Wa2   = (const float*)d_in[7]  + (size_t)2 * FDIM * HDIM;
    const float* asa   = (const float*)d_in[8]  + 2 * HDIM;
    const float* ada   = (const float*)d_in[9]  + 2 * HDIM;
    const float* ba    = (const float*)d_in[10] + 2 * HDIM;
    const float* Wb2   = (const float*)d_in[11] + (size_t)2 * HDIM * FDIM;
    const float* asb   = (const float*)d_in[12] + 2 * FDIM;
    const float* adb   = (const float*)d_in[13] + 2 * FDIM;
    const float* bb    = (const float*)d_in[14] + 2 * FDIM;
    const float* Wout  = (const float*)d_in[21];
    const float* bout  = (const float*)d_in[22];
    float* out = (float*)d_out;

    const int* e_src = eippi;
    const int* e_dst = eippi + EPPI;

    float *agg, *pas, *pad, *pq, *ps1, *ps2, *pvas, *pvad, *pcb, *phb;
    int *deg, *rowptr, *cursor, *nbr, *bsum;
    cudaGetSymbolAddress((void**)&agg,    g_agg);
    cudaGetSymbolAddress((void**)&pas,    g_as);
    cudaGetSymbolAddress((void**)&pad,    g_ad);
    cudaGetSymbolAddress((void**)&pq,     g_q);
    cudaGetSymbolAddress((void**)&ps1,    g_s1);
    cudaGetSymbolAddress((void**)&ps2,    g_s2);
    cudaGetSymbolAddress((void**)&pvas,   g_vas);
    cudaGetSymbolAddress((void**)&pvad,   g_vad);
    cudaGetSymbolAddress((void**)&pcb,    g_cb);
    cudaGetSymbolAddress((void**)&phb,    g_hb);
    cudaGetSymbolAddress((void**)&deg,    g_deg);
    cudaGetSymbolAddress((void**)&rowptr, g_rowptr);
    cudaGetSymbolAddress((void**)&cursor, g_cursor);
    cudaGetSymbolAddress((void**)&nbr,    g_nbr);
    cudaGetSymbolAddress((void**)&bsum,   g_bsum);

    const int T = 256;
    const int edgeBlocks  = (ETOT + T - 1) / T;
    const int nodeBlocks  = (NPV + T - 1) / T;
    const int warpNodeBlk = (NPV * 32 + T - 1) / T;
    const int scanBlocks  = (NPV + SCB - 1) / SCB;

    // ===== CSR build (shared by both layers) =====
    zero_i<<<nodeBlocks, T>>>(deg, NPV);
    count_k<<<edgeBlocks, T>>>(e_src, e_dst, deg);
    scan_block_k<<<scanBlocks, SCB>>>(deg, rowptr, bsum, NPV);
    scan_bsum_k<<<1, SCB>>>(bsum, scanBlocks);
    scan_add_k<<<nodeBlocks, T>>>(rowptr, cursor, bsum, NPV);
    place_k<<<edgeBlocks, T>>>(e_src, e_dst, cursor, nbr);

    // ===== precompute folded vectors + zero scalar accumulators =====
    setup_vecs_k<<<49, 256>>>(Wa2, asa, ada, Wb2, asb, adb, Wout, bb,
                              pvas, pvad, pcb, phb);
    zero_f<<<(4 * NPV + T - 1) / T, T>>>(pq, 4 * NPV);

    // ===== layer a: gather xp, GEMM with fused relu + layer-b scalar dots ====
    attn_dots_k<<<warpNodeBlk, T>>>(xp, pvas, pvad, pas, pad);
    gather_feat_k<<<warpNodeBlk, T>>>(rowptr, nbr, pas, pad, xp, agg);
    gemm_fused_k<<<dim3(HDIM / 128, (NPV + 127) / 128), 256>>>(
        agg, Wa2, ba, pcb, pq, NPV, HDIM, FDIM);

    // ===== layer b (scalar-only) + head =====
    gather_scalar_k<<<warpNodeBlk, T>>>(rowptr, nbr, pq, phb, ps1, ps2);
    pair_head_k<<<(NPAIRS + T - 1) / T, T>>>(mask, ps1, ps2, bout, out);
}